// round 7
// baseline (speedup 1.0000x reference)
#include <cuda_runtime.h>
#include <cstdint>

#define NB    64
#define NTH   512
#define PCW   36                 // packed cols: 32 + 2+2 halo (pair = x, x+32)
#define PRW   68                 // rows: 64 + 2+2 halo
#define PKBUF (PRW*PCW)          // 2448 float2
#define NPIX  4096

__device__ float g_T[104];   // LUT[tap][symbol], symbol 3 = zero pad
__device__ float g_effb;

// ---------------------------------------------------------------------------
// Prep: collapse encode_w(150x2x5x5)+r_w(150)+emb(3x2) -> 25-tap x 4-symbol LUT
// ---------------------------------------------------------------------------
__global__ void prep_kernel(const float* __restrict__ emb,
                            const float* __restrict__ encode_w,
                            const float* __restrict__ encode_b,
                            const float* __restrict__ r_w) {
    __shared__ float effw[50];
    int t = threadIdx.x;
    if (t < 50) {
        float s = 0.f;
        for (int c = 0; c < 150; ++c) s = fmaf(r_w[c], encode_w[c * 50 + t], s);
        effw[t] = s;
    }
    __syncthreads();
    if (t < 25) {
        float w0 = effw[t], w1 = effw[25 + t];
        #pragma unroll
        for (int z = 0; z < 3; ++z)
            g_T[t * 4 + z] = w0 * emb[2 * z] + w1 * emb[2 * z + 1];
        g_T[t * 4 + 3] = 0.f;
    } else if (t == 32) {
        float s = 0.f;
        for (int c = 0; c < 150; ++c) s = fmaf(r_w[c], encode_b[c], s);
        g_effb = s;
    }
}

// ---- packed f32x2 FMA (FFMA2 — only reachable via PTX) ---------------------
union F2U { float2 f; unsigned long long u; };
__device__ __forceinline__ float2 ffma2(float2 a, float2 b, float2 c) {
    F2U A, B, C, D; A.f = a; B.f = b; C.f = c;
    asm("fma.rn.f32x2 %0, %1, %2, %3;" : "=l"(D.u) : "l"(A.u), "l"(B.u), "l"(C.u));
    return D.f;
}

// ---------------------------------------------------------------------------
// Fused VIN: 1 CTA per image, 512 threads. Pixel pairs (x, x+32) packed into
// float2 SMEM lanes; all conv arithmetic in FFMA2. Thread: x' = tid&31,
// strip s = tid>>5 owns image rows 4s..4s+3.
// Packed buffer col ci holds (v[ci-2], v[ci+30]); ci 0,1 lo and ci 34,35 hi
// are permanent zeros (x-padding); seam values duplicated by threads 0,1,30,31.
// ---------------------------------------------------------------------------
__global__ __launch_bounds__(NTH, 1)
void vin_kernel(const int* __restrict__ maze,
                const float* __restrict__ q_w,
                const float* __restrict__ w_in,
                const float* __restrict__ fc_w,
                float* __restrict__ out) {
    extern __shared__ float2 sm2[];
    float2* bufA = sm2;                    // v ping
    float2* bufB = sm2 + PKBUF;            // v pong
    float2* r2   = sm2 + 2 * PKBUF;        // packed r
    float2* Rq2  = sm2 + 3 * PKBUF;        // [8][64][32] packed, 128KB
    float2* qw2  = Rq2 + 8 * 64 * 32;      // 200 (c,c) pairs
    float2* w2   = qw2 + 200;              // 200 (c,c) pairs
    float2* fc2  = w2 + 200;               // 32 (f,f) pairs
    float*  T_s  = (float*)(fc2 + 32);     // 104

    const int tid = threadIdx.x;
    const int b   = blockIdx.x;
    const int x   = tid & 31;
    const int s   = tid >> 5;              // 0..15
    const int r0  = s << 2;                // image row base

    int* m_tile = (int*)Rq2;               // 68x68 ints, alias (dead before Rq2 use)

    const float2 z2 = make_float2(0.f, 0.f);
    for (int i = tid; i < PKBUF; i += NTH) { bufA[i] = z2; bufB[i] = z2; r2[i] = z2; }
    for (int i = tid; i < 68 * 68; i += NTH) m_tile[i] = 3;
    for (int i = tid; i < 200; i += NTH) {
        float c = q_w[i];  qw2[i] = make_float2(c, c);
        float cc = w_in[i]; w2[i] = make_float2(cc, cc);
    }
    if (tid < 104) T_s[tid] = g_T[tid];
    if (tid < 32) { float f = fc_w[tid]; fc2[tid] = make_float2(f, f); }
    __syncthreads();

    const int* mz = maze + b * NPIX;
    for (int i = tid; i < NPIX; i += NTH)
        m_tile[((i >> 6) + 2) * 68 + (i & 63) + 2] = mz[i];
    __syncthreads();

    // --- phase 1: r via LUT, scattered into packed layout (+ seam dups)
    {
        const float effb = g_effb;
        for (int p = tid; p < NPIX; p += NTH) {
            int y = p >> 6, xx = p & 63;
            float acc = effb;
            #pragma unroll
            for (int ky = 0; ky < 5; ++ky)
                #pragma unroll
                for (int kx = 0; kx < 5; ++kx)
                    acc += T_s[(ky * 5 + kx) * 4 + m_tile[(y + ky) * 68 + xx + kx]];
            float* base = (float*)(r2 + (y + 2) * PCW);
            if (xx < 32) base[2 * (xx + 2)]      = acc;   // lo of ci=xx+2
            else         base[2 * (xx - 30) + 1] = acc;   // hi of ci=xx-30
            if (xx == 30 || xx == 31) base[2 * (xx - 30) + 1] = acc;  // ci 0,1 hi
            if (xx == 32 || xx == 33) base[2 * (xx + 2)]      = acc;  // ci 34,35 lo
        }
    }
    __syncthreads();   // m_tile dead; Rq2 writable

    // --- phase 2: Rq = conv(r, q_w) kept packed in SMEM; v1 = max_a Rq
    {
        float2 vw[8][5];
        #pragma unroll
        for (int dy = 0; dy < 8; ++dy)
            #pragma unroll
            for (int dx = 0; dx < 5; ++dx)
                vw[dy][dx] = r2[(r0 + dy) * PCW + x + dx];
        float2 vmax[4];
        #pragma unroll
        for (int j = 0; j < 4; ++j) vmax[j] = make_float2(-3.0e38f, -3.0e38f);
        #pragma unroll 1
        for (int a = 0; a < 8; ++a) {
            float2 acc[4] = {z2, z2, z2, z2};
            const float2* cw = qw2 + a * 25;
            #pragma unroll
            for (int ky = 0; ky < 5; ++ky)
                #pragma unroll
                for (int kx = 0; kx < 5; ++kx) {
                    float2 c = cw[ky * 5 + kx];
                    #pragma unroll
                    for (int j = 0; j < 4; ++j)
                        acc[j] = ffma2(c, vw[j + ky][kx], acc[j]);
                }
            float2* rqa = Rq2 + a * 2048;
            #pragma unroll
            for (int j = 0; j < 4; ++j) {
                rqa[(r0 + j) * 32 + x] = acc[j];
                vmax[j].x = fmaxf(vmax[j].x, acc[j].x);
                vmax[j].y = fmaxf(vmax[j].y, acc[j].y);
            }
        }
        #pragma unroll
        for (int j = 0; j < 4; ++j) {
            float2* row = bufA + (r0 + j + 2) * PCW;
            row[x + 2] = vmax[j];
            float* rowf = (float*)row;
            if (x == 30) rowf[1]  = vmax[j].x;   // ci0 hi  = v[30]
            if (x == 31) rowf[3]  = vmax[j].x;   // ci1 hi  = v[31]
            if (x == 0)  rowf[68] = vmax[j].y;   // ci34 lo = v[32]
            if (x == 1)  rowf[70] = vmax[j].y;   // ci35 lo = v[33]
        }
    }
    __syncthreads();

    // --- 9 value-iteration steps, all FFMA2, Rq2 as accumulator init
    float2* vin2  = bufA;
    float2* vout2 = bufB;
    for (int t = 0; t < 9; ++t) {
        float2 vw[8][5];
        #pragma unroll
        for (int dy = 0; dy < 8; ++dy)
            #pragma unroll
            for (int dx = 0; dx < 5; ++dx)
                vw[dy][dx] = vin2[(r0 + dy) * PCW + x + dx];
        float2 vmax[4];
        #pragma unroll
        for (int j = 0; j < 4; ++j) vmax[j] = make_float2(-3.0e38f, -3.0e38f);
        #pragma unroll 1
        for (int a = 0; a < 8; ++a) {
            const float2* rqa = Rq2 + a * 2048 + r0 * 32 + x;
            float2 acc[4];
            #pragma unroll
            for (int j = 0; j < 4; ++j) acc[j] = rqa[j * 32];
            const float2* cw = w2 + a * 25;
            #pragma unroll
            for (int ky = 0; ky < 5; ++ky)
                #pragma unroll
                for (int kx = 0; kx < 5; ++kx) {
                    float2 c = cw[ky * 5 + kx];
                    #pragma unroll
                    for (int j = 0; j < 4; ++j)
                        acc[j] = ffma2(c, vw[j + ky][kx], acc[j]);
                }
            #pragma unroll
            for (int j = 0; j < 4; ++j) {
                vmax[j].x = fmaxf(vmax[j].x, acc[j].x);
                vmax[j].y = fmaxf(vmax[j].y, acc[j].y);
            }
        }
        #pragma unroll
        for (int j = 0; j < 4; ++j) {
            float2* row = vout2 + (r0 + j + 2) * PCW;
            row[x + 2] = vmax[j];
            float* rowf = (float*)row;
            if (x == 30) rowf[1]  = vmax[j].x;
            if (x == 31) rowf[3]  = vmax[j].x;
            if (x == 0)  rowf[68] = vmax[j].y;
            if (x == 1)  rowf[70] = vmax[j].y;
        }
        __syncthreads();
        float2* tmp = vin2; vin2 = vout2; vout2 = tmp;
    }

    // --- final step folded into fc matvec (per-row to cap registers)
    {
        float4* op = (float4*)(out + (size_t)b * NPIX * 4);
        #pragma unroll 1
        for (int j = 0; j < 4; ++j) {
            const int yrow = r0 + j;
            float2 vw[5][5];
            #pragma unroll
            for (int dy = 0; dy < 5; ++dy)
                #pragma unroll
                for (int dx = 0; dx < 5; ++dx)
                    vw[dy][dx] = vin2[(yrow + dy) * PCW + x + dx];
            float2 o0 = z2, o1 = z2, o2 = z2, o3 = z2;
            #pragma unroll 1
            for (int a = 0; a < 8; ++a) {
                float2 acc = Rq2[a * 2048 + yrow * 32 + x];
                const float2* cw = w2 + a * 25;
                #pragma unroll
                for (int ky = 0; ky < 5; ++ky)
                    #pragma unroll
                    for (int kx = 0; kx < 5; ++kx)
                        acc = ffma2(cw[ky * 5 + kx], vw[ky][kx], acc);
                o0 = ffma2(fc2[a],      acc, o0);
                o1 = ffma2(fc2[8 + a],  acc, o1);
                o2 = ffma2(fc2[16 + a], acc, o2);
                o3 = ffma2(fc2[24 + a], acc, o3);
            }
            op[yrow * 64 + x]      = make_float4(o0.x, o1.x, o2.x, o3.x);
            op[yrow * 64 + x + 32] = make_float4(o0.y, o1.y, o2.y, o3.y);
        }
    }
}

// ---------------------------------------------------------------------------
extern "C" void kernel_launch(void* const* d_in, const int* in_sizes, int n_in,
                              void* d_out, int out_size) {
    const int*   maze     = (const int*)d_in[0];
    const float* emb      = (const float*)d_in[1];
    const float* encode_w = (const float*)d_in[2];
    const float* encode_b = (const float*)d_in[3];
    const float* r_w      = (const float*)d_in[4];
    const float* q_w      = (const float*)d_in[5];
    const float* w_in     = (const float*)d_in[6];
    const float* fc_w     = (const float*)d_in[7];
    float* out = (float*)d_out;

    prep_kernel<<<1, 64>>>(emb, encode_w, encode_b, r_w);

    const int smem_bytes = (3 * PKBUF + 8 * 64 * 32 + 200 + 200 + 32) * 8 + 104 * 4;
    cudaFuncSetAttribute(vin_kernel,
                         cudaFuncAttributeMaxDynamicSharedMemorySize, smem_bytes);
    vin_kernel<<<NB, NTH, smem_bytes>>>(maze, q_w, w_in, fc_w, out);
}

// round 9
// speedup vs baseline: 1.1636x; 1.1636x over previous
#include <cuda_runtime.h>
#include <cstdint>

#define NB     64
#define NTH    832        // 13 strips x 64 cols
#define BW     68         // 64 + 2+2 col halo
#define BR     60         // buffer rows: extent 52 + generous pad, l in [-4,56)
#define BUFSZ  (BR*BW)    // 4080
#define EXT    52         // computed extent rows per CTA
#define NPIX   4096

__device__ float g_T[104];   // LUT[tap][symbol], symbol 3 = zero pad
__device__ float g_effb;

// ---------------------------------------------------------------------------
// Prep: collapse encode_w(150x2x5x5)+r_w(150)+emb(3x2) -> 25-tap x 4-symbol LUT
// ---------------------------------------------------------------------------
__global__ void prep_kernel(const float* __restrict__ emb,
                            const float* __restrict__ encode_w,
                            const float* __restrict__ encode_b,
                            const float* __restrict__ r_w) {
    __shared__ float effw[50];
    int t = threadIdx.x;
    if (t < 50) {
        float s = 0.f;
        for (int c = 0; c < 150; ++c) s = fmaf(r_w[c], encode_w[c * 50 + t], s);
        effw[t] = s;
    }
    __syncthreads();
    if (t < 25) {
        float w0 = effw[t], w1 = effw[25 + t];
        #pragma unroll
        for (int z = 0; z < 3; ++z)
            g_T[t * 4 + z] = w0 * emb[2 * z] + w1 * emb[2 * z + 1];
        g_T[t * 4 + 3] = 0.f;
    } else if (t == 32) {
        float s = 0.f;
        for (int c = 0; c < 150; ++c) s = fmaf(r_w[c], encode_b[c], s);
        g_effb = s;
    }
}

// ---------------------------------------------------------------------------
// Ghost-zone VIN: 2 independent CTAs per image (no cluster, no comm).
// rank0 owns rows [0,32), computes extent rows [0,52).
// rank1 owns rows [32,64), computes extent rows [12,64)  (local l = g - 12).
// Buffers: local row l stored at buffer row l+4; image col c at buffer col c+2.
// 832 threads: x = tid mod 64, strip s = tid/64 owns local rows 4s..4s+3.
// ---------------------------------------------------------------------------
__global__ __launch_bounds__(NTH, 1)
void vin_kernel(const int* __restrict__ maze,
                const float* __restrict__ q_w,
                const float* __restrict__ w_in,
                const float* __restrict__ fc_w,
                float* __restrict__ out) {
    extern __shared__ float sm[];
    float* bufA = sm;                    // v ping
    float* bufB = sm + BUFSZ;            // v pong
    float* r_s  = sm + 2 * BUFSZ;        // r
    float* Rq_s = sm + 3 * BUFSZ;        // [8][52][64]
    float* T_s  = Rq_s + 8 * EXT * 64;   // 104
    float* qw_s = T_s + 104;             // 200
    float* w_s  = qw_s + 200;            // 200
    float* fc_s = w_s + 200;             // 32

    const int tid  = threadIdx.x;
    const int b    = blockIdx.x >> 1;
    const int rank = blockIdx.x & 1;
    const int base = rank ? 12 : 0;      // global row of local l=0
    const int x    = tid & 63;
    const int s    = tid >> 6;           // 0..12
    const int l0   = s << 2;             // first local output row of strip

    int* m_tile = (int*)Rq_s;            // 60x68 ints alias (dead before Rq use)

    // --- init
    for (int i = tid; i < BUFSZ; i += NTH) { bufA[i] = 0.f; bufB[i] = 0.f; r_s[i] = 0.f; }
    for (int i = tid; i < BUFSZ; i += NTH) m_tile[i] = 3;
    for (int i = tid; i < 200; i += NTH) { qw_s[i] = q_w[i]; w_s[i] = w_in[i]; }
    if (tid < 104) T_s[tid] = g_T[tid];
    if (tid < 32)  fc_s[tid] = fc_w[tid];
    __syncthreads();

    // maze rows: global g = base-4+lr, lr in [0,60)
    const int* mz = maze + b * NPIX;
    for (int i = tid; i < BR * 64; i += NTH) {
        int lr = i >> 6;
        int g  = base - 4 + lr;
        int c  = i & 63;
        if (g >= 0 && g < 64)
            m_tile[lr * BW + c + 2] = mz[g * 64 + c];
    }
    __syncthreads();

    // --- phase 1: r via LUT over local rows l in [-2,54) (in-image only)
    {
        const float effb = g_effb;
        for (int p = tid; p < 56 * 64; p += NTH) {
            int lr = p >> 6;             // l = lr - 2
            int g  = base + lr - 2;
            int xx = p & 63;
            if (g < 0 || g >= 64) continue;
            float acc = effb;
            #pragma unroll
            for (int ky = 0; ky < 5; ++ky)
                #pragma unroll
                for (int kx = 0; kx < 5; ++kx)
                    acc += T_s[(ky * 5 + kx) * 4 + m_tile[(lr + ky) * BW + xx + kx]];
            r_s[(lr + 2) * BW + xx + 2] = acc;   // buffer row l+4 = lr+2
        }
    }
    __syncthreads();   // m_tile dead; Rq writable

    // --- phase 2: Rq = conv(r, q_w), v1 = max_a Rq, over full extent [0,52)
    {
        float vw[8][5];
        #pragma unroll
        for (int dy = 0; dy < 8; ++dy)
            #pragma unroll
            for (int dx = 0; dx < 5; ++dx)
                vw[dy][dx] = r_s[(l0 + 2 + dy) * BW + x + dx];
        float vmax[4];
        #pragma unroll
        for (int a = 0; a < 8; ++a) {
            float acc[4] = {0.f, 0.f, 0.f, 0.f};
            #pragma unroll
            for (int ky = 0; ky < 5; ++ky)
                #pragma unroll
                for (int kx = 0; kx < 5; ++kx) {
                    float c = qw_s[a * 25 + ky * 5 + kx];
                    #pragma unroll
                    for (int j = 0; j < 4; ++j)
                        acc[j] = fmaf(c, vw[j + ky][kx], acc[j]);
                }
            #pragma unroll
            for (int j = 0; j < 4; ++j) {
                Rq_s[a * (EXT * 64) + (l0 + j) * 64 + x] = acc[j];
                vmax[j] = (a == 0) ? acc[j] : fmaxf(vmax[j], acc[j]);
            }
        }
        #pragma unroll
        for (int j = 0; j < 4; ++j)
            bufA[(l0 + j + 4) * BW + x + 2] = vmax[j];
    }
    __syncthreads();

    // --- 9 value-iteration steps; valid region shrinks 2 rows/step from the
    //     interior edge (top for rank0, bottom for rank1).
    float* vin  = bufA;
    float* vout = bufB;
    #pragma unroll 1
    for (int t = 0; t < 9; ++t) {
        const int lo = rank ? 2 * (t + 1) : 0;
        const int hi = rank ? EXT : 50 - 2 * t;
        if (l0 + 3 >= lo && l0 < hi) {
            float vw[8][5];
            #pragma unroll
            for (int dy = 0; dy < 8; ++dy)
                #pragma unroll
                for (int dx = 0; dx < 5; ++dx)
                    vw[dy][dx] = vin[(l0 + 2 + dy) * BW + x + dx];
            float vmax[4];
            #pragma unroll
            for (int a = 0; a < 8; ++a) {
                const float* rqa = Rq_s + a * (EXT * 64) + l0 * 64 + x;
                float acc[4];
                #pragma unroll
                for (int j = 0; j < 4; ++j) acc[j] = rqa[j * 64];
                #pragma unroll
                for (int ky = 0; ky < 5; ++ky)
                    #pragma unroll
                    for (int kx = 0; kx < 5; ++kx) {
                        float c = w_s[a * 25 + ky * 5 + kx];
                        #pragma unroll
                        for (int j = 0; j < 4; ++j)
                            acc[j] = fmaf(c, vw[j + ky][kx], acc[j]);
                    }
                #pragma unroll
                for (int j = 0; j < 4; ++j)
                    vmax[j] = (a == 0) ? acc[j] : fmaxf(vmax[j], acc[j]);
            }
            #pragma unroll
            for (int j = 0; j < 4; ++j) {
                int l = l0 + j;
                if (l >= lo && l < hi)
                    vout[(l + 4) * BW + x + 2] = vmax[j];
            }
        }
        __syncthreads();
        float* tmp = vin; vin = vout; vout = tmp;
    }

    // --- final conv folded into fc matvec; own rows only
    //     rank0: strips 0..7 (l 0..31); rank1: strips 5..12 (l 20..51)
    if (rank ? (s >= 5) : (s < 8)) {
        float4* op = (float4*)(out + (size_t)b * NPIX * 4);
        #pragma unroll 1
        for (int j = 0; j < 4; ++j) {
            const int l = l0 + j;
            float vw[5][5];
            #pragma unroll
            for (int dy = 0; dy < 5; ++dy)
                #pragma unroll
                for (int dx = 0; dx < 5; ++dx)
                    vw[dy][dx] = vin[(l + 2 + dy) * BW + x + dx];
            float o0 = 0.f, o1 = 0.f, o2 = 0.f, o3 = 0.f;
            #pragma unroll
            for (int a = 0; a < 8; ++a) {
                float acc = Rq_s[a * (EXT * 64) + l * 64 + x];
                #pragma unroll
                for (int ky = 0; ky < 5; ++ky)
                    #pragma unroll
                    for (int kx = 0; kx < 5; ++kx)
                        acc = fmaf(w_s[a * 25 + ky * 5 + kx], vw[ky][kx], acc);
                o0 = fmaf(fc_s[a],      acc, o0);
                o1 = fmaf(fc_s[8 + a],  acc, o1);
                o2 = fmaf(fc_s[16 + a], acc, o2);
                o3 = fmaf(fc_s[24 + a], acc, o3);
            }
            op[(base + l) * 64 + x] = make_float4(o0, o1, o2, o3);
        }
    }
}

// ---------------------------------------------------------------------------
extern "C" void kernel_launch(void* const* d_in, const int* in_sizes, int n_in,
                              void* d_out, int out_size) {
    const int*   maze     = (const int*)d_in[0];
    const float* emb      = (const float*)d_in[1];
    const float* encode_w = (const float*)d_in[2];
    const float* encode_b = (const float*)d_in[3];
    const float* r_w      = (const float*)d_in[4];
    const float* q_w      = (const float*)d_in[5];
    const float* w_in     = (const float*)d_in[6];
    const float* fc_w     = (const float*)d_in[7];
    float* out = (float*)d_out;

    prep_kernel<<<1, 64>>>(emb, encode_w, encode_b, r_w);

    const int smem_bytes = (3 * BUFSZ + 8 * EXT * 64 + 104 + 200 + 200 + 32)
                           * (int)sizeof(float);
    cudaFuncSetAttribute(vin_kernel,
                         cudaFuncAttributeMaxDynamicSharedMemorySize, smem_bytes);
    vin_kernel<<<NB * 2, NTH, smem_bytes>>>(maze, q_w, w_in, fc_w, out);
}